// round 2
// baseline (speedup 1.0000x reference)
#include <cuda_runtime.h>
#include <cuda_bf16.h>
#include <math.h>

#define NLEV 16
#define TBL (1u << 19)

// floor(16 * 1.3819^l) computed in double precision
__device__ __constant__ int c_res[16] = {16, 22, 30, 42, 58, 80, 111, 153,
                                         212, 294, 406, 561, 775, 1072, 1481, 2047};

__global__ __launch_bounds__(128)
void nerf_fused_kernel(const float* __restrict__ xyz,
                       const float* __restrict__ dirp,
                       const float* __restrict__ table,
                       const float* __restrict__ w1,
                       const float* __restrict__ w2,
                       const float* __restrict__ wr1,
                       const float* __restrict__ wr2,
                       const float* __restrict__ wr3,
                       float* __restrict__ out, int N)
{
    __shared__ __align__(16) float sW1[32 * 64];
    __shared__ __align__(16) float sW2[64 * 20];   // 64x17 padded to stride 20
    __shared__ __align__(16) float sR1[32 * 64];
    __shared__ __align__(16) float sR2[64 * 64];
    __shared__ __align__(16) float sR3[64 * 4];    // 64x3 padded to stride 4

    const int tid = threadIdx.x;
    for (int i = tid; i < 32 * 64; i += 128) sW1[i] = w1[i];
    for (int i = tid; i < 64 * 20; i += 128) {
        int r = i / 20, c = i % 20;
        sW2[i] = (c < 17) ? w2[r * 17 + c] : 0.0f;
    }
    for (int i = tid; i < 32 * 64; i += 128) sR1[i] = wr1[i];
    for (int i = tid; i < 64 * 64; i += 128) sR2[i] = wr2[i];
    for (int i = tid; i < 64 * 4; i += 128) {
        int r = i / 4, c = i % 4;
        sR3[i] = (c < 3) ? wr3[r * 3 + c] : 0.0f;
    }
    __syncthreads();

    const int idx = blockIdx.x * 128 + tid;
    if (idx >= N) return;

    const float x = xyz[3 * idx + 0];
    const float y = xyz[3 * idx + 1];
    const float z = xyz[3 * idx + 2];

    // ---------------- hash grid encode: 32 features ----------------
    float enc[32];
    #pragma unroll
    for (int l = 0; l < NLEV; l++) {
        const int res = c_res[l];
        const float rf = (float)res;
        const float px = x * rf, py = y * rf, pz = z * rf;
        const float fx = floorf(px), fy = floorf(py), fz = floorf(pz);
        const float wx = px - fx, wy = py - fy, wz = pz - fz;
        const unsigned X = (unsigned)fx, Y = (unsigned)fy, Z = (unsigned)fz;

        unsigned id0, id1, id2, id3, id4, id5, id6, id7;
        if (l < 5) {   // dense levels
            const unsigned s  = (unsigned)(res + 1);
            const unsigned s2 = s * s;
            const unsigned base = X + Y * s + Z * s2;
            id0 = base;          id1 = base + 1u;
            id2 = base + s;      id3 = base + s + 1u;
            id4 = base + s2;     id5 = base + s2 + 1u;
            id6 = base + s2 + s; id7 = base + s2 + s + 1u;
        } else {       // hashed levels
            const unsigned P1 = 2654435761u, P2 = 805459861u;
            const unsigned hx0 = X, hx1 = X + 1u;
            const unsigned hy0 = Y * P1, hy1 = (Y + 1u) * P1;
            const unsigned hz0 = Z * P2, hz1 = (Z + 1u) * P2;
            const unsigned M = TBL - 1u;
            id0 = (hx0 ^ hy0 ^ hz0) & M;  id1 = (hx1 ^ hy0 ^ hz0) & M;
            id2 = (hx0 ^ hy1 ^ hz0) & M;  id3 = (hx1 ^ hy1 ^ hz0) & M;
            id4 = (hx0 ^ hy0 ^ hz1) & M;  id5 = (hx1 ^ hy0 ^ hz1) & M;
            id6 = (hx0 ^ hy1 ^ hz1) & M;  id7 = (hx1 ^ hy1 ^ hz1) & M;
        }

        const float2* tl = (const float2*)table + (size_t)l * TBL;
        const float2 f0 = __ldg(tl + id0);
        const float2 f1 = __ldg(tl + id1);
        const float2 f2 = __ldg(tl + id2);
        const float2 f3 = __ldg(tl + id3);
        const float2 f4 = __ldg(tl + id4);
        const float2 f5 = __ldg(tl + id5);
        const float2 f6 = __ldg(tl + id6);
        const float2 f7 = __ldg(tl + id7);

        const float wx0 = 1.0f - wx, wy0 = 1.0f - wy, wz0 = 1.0f - wz;
        const float w00 = wy0 * wz0, w10 = wy * wz0, w01 = wy0 * wz, w11 = wy * wz;
        const float c0 = wx0 * w00, c1 = wx * w00;
        const float c2 = wx0 * w10, c3 = wx * w10;
        const float c4 = wx0 * w01, c5 = wx * w01;
        const float c6 = wx0 * w11, c7 = wx * w11;

        float e0 = f0.x * c0; float e1 = f0.y * c0;
        e0 = fmaf(f1.x, c1, e0); e1 = fmaf(f1.y, c1, e1);
        e0 = fmaf(f2.x, c2, e0); e1 = fmaf(f2.y, c2, e1);
        e0 = fmaf(f3.x, c3, e0); e1 = fmaf(f3.y, c3, e1);
        e0 = fmaf(f4.x, c4, e0); e1 = fmaf(f4.y, c4, e1);
        e0 = fmaf(f5.x, c5, e0); e1 = fmaf(f5.y, c5, e1);
        e0 = fmaf(f6.x, c6, e0); e1 = fmaf(f6.y, c6, e1);
        e0 = fmaf(f7.x, c7, e0); e1 = fmaf(f7.y, c7, e1);
        enc[2 * l + 0] = e0;
        enc[2 * l + 1] = e1;
    }

    // ---------------- sigma MLP: 32 -> 64 (relu) -> 17 ----------------
    float h[64];
    #pragma unroll
    for (int j = 0; j < 64; j += 4) {
        float a0 = 0.f, a1 = 0.f, a2 = 0.f, a3 = 0.f;
        #pragma unroll
        for (int i = 0; i < 32; i++) {
            const float4 wv = *(const float4*)(sW1 + i * 64 + j);
            a0 = fmaf(enc[i], wv.x, a0);
            a1 = fmaf(enc[i], wv.y, a1);
            a2 = fmaf(enc[i], wv.z, a2);
            a3 = fmaf(enc[i], wv.w, a3);
        }
        h[j + 0] = fmaxf(a0, 0.f);
        h[j + 1] = fmaxf(a1, 0.f);
        h[j + 2] = fmaxf(a2, 0.f);
        h[j + 3] = fmaxf(a3, 0.f);
    }

    float g[20];
    #pragma unroll
    for (int j = 0; j < 20; j += 4) {
        float a0 = 0.f, a1 = 0.f, a2 = 0.f, a3 = 0.f;
        #pragma unroll
        for (int i = 0; i < 64; i++) {
            const float4 wv = *(const float4*)(sW2 + i * 20 + j);
            a0 = fmaf(h[i], wv.x, a0);
            a1 = fmaf(h[i], wv.y, a1);
            a2 = fmaf(h[i], wv.z, a2);
            a3 = fmaf(h[i], wv.w, a3);
        }
        g[j + 0] = a0; g[j + 1] = a1; g[j + 2] = a2; g[j + 3] = a3;
    }
    const float sigma = g[0];   // g[1..16] = geo_feat

    // ---------------- SH encode of direction ----------------
    const float dx = dirp[3 * idx + 0] * 2.0f - 1.0f;
    const float dy = dirp[3 * idx + 1] * 2.0f - 1.0f;
    const float dz = dirp[3 * idx + 2] * 2.0f - 1.0f;
    const float x2 = dx * dx, y2 = dy * dy, z2 = dz * dz;
    const float xy = dx * dy, yz = dy * dz, xz = dx * dz;

    float rin[32];
    rin[0]  = 0.28209479177387814f;
    rin[1]  = -0.48860251190291987f * dy;
    rin[2]  = 0.48860251190291987f * dz;
    rin[3]  = -0.48860251190291987f * dx;
    rin[4]  = 1.0925484305920792f * xy;
    rin[5]  = -1.0925484305920792f * yz;
    rin[6]  = 0.94617469575756f * z2 - 0.31539156525252f;
    rin[7]  = -1.0925484305920792f * xz;
    rin[8]  = 0.5462742152960396f * (x2 - y2);
    rin[9]  = 0.5900435899266435f * dy * (-3.0f * x2 + y2);
    rin[10] = 2.890611442640554f * xy * dz;
    rin[11] = 0.4570457994644657f * dy * (1.0f - 5.0f * z2);
    rin[12] = 0.3731763325901154f * dz * (5.0f * z2 - 3.0f);
    rin[13] = 0.4570457994644657f * dx * (1.0f - 5.0f * z2);
    rin[14] = 1.445305721320277f * dz * (x2 - y2);
    rin[15] = 0.5900435899266435f * dx * (-x2 + 3.0f * y2);
    #pragma unroll
    for (int i = 0; i < 16; i++) rin[16 + i] = g[1 + i];

    // ---------------- rgb MLP: 32 -> 64 (relu) -> 64 (relu) -> 3 ----------------
    #pragma unroll
    for (int j = 0; j < 64; j += 4) {
        float a0 = 0.f, a1 = 0.f, a2 = 0.f, a3 = 0.f;
        #pragma unroll
        for (int i = 0; i < 32; i++) {
            const float4 wv = *(const float4*)(sR1 + i * 64 + j);
            a0 = fmaf(rin[i], wv.x, a0);
            a1 = fmaf(rin[i], wv.y, a1);
            a2 = fmaf(rin[i], wv.z, a2);
            a3 = fmaf(rin[i], wv.w, a3);
        }
        h[j + 0] = fmaxf(a0, 0.f);
        h[j + 1] = fmaxf(a1, 0.f);
        h[j + 2] = fmaxf(a2, 0.f);
        h[j + 3] = fmaxf(a3, 0.f);
    }

    float h2[64];
    #pragma unroll
    for (int j = 0; j < 64; j += 4) {
        float a0 = 0.f, a1 = 0.f, a2 = 0.f, a3 = 0.f;
        #pragma unroll
        for (int i = 0; i < 64; i++) {
            const float4 wv = *(const float4*)(sR2 + i * 64 + j);
            a0 = fmaf(h[i], wv.x, a0);
            a1 = fmaf(h[i], wv.y, a1);
            a2 = fmaf(h[i], wv.z, a2);
            a3 = fmaf(h[i], wv.w, a3);
        }
        h2[j + 0] = fmaxf(a0, 0.f);
        h2[j + 1] = fmaxf(a1, 0.f);
        h2[j + 2] = fmaxf(a2, 0.f);
        h2[j + 3] = fmaxf(a3, 0.f);
    }

    float r0 = 0.f, r1 = 0.f, r2 = 0.f;
    #pragma unroll
    for (int i = 0; i < 64; i++) {
        const float4 wv = *(const float4*)(sR3 + i * 4);
        r0 = fmaf(h2[i], wv.x, r0);
        r1 = fmaf(h2[i], wv.y, r1);
        r2 = fmaf(h2[i], wv.z, r2);
    }

    // ---------------- outputs: sigmoid(rgb) [N,3], relu(sigma) [N,1] ----------------
    out[3 * idx + 0] = 1.0f / (1.0f + expf(-r0));
    out[3 * idx + 1] = 1.0f / (1.0f + expf(-r1));
    out[3 * idx + 2] = 1.0f / (1.0f + expf(-r2));
    out[(size_t)3 * N + idx] = fmaxf(sigma, 0.f);
}

extern "C" void kernel_launch(void* const* d_in, const int* in_sizes, int n_in,
                              void* d_out, int out_size)
{
    const float* xyz   = (const float*)d_in[0];
    const float* dirp  = (const float*)d_in[1];
    const float* table = (const float*)d_in[2];
    const float* w1    = (const float*)d_in[3];
    const float* w2    = (const float*)d_in[4];
    const float* wr1   = (const float*)d_in[5];
    const float* wr2   = (const float*)d_in[6];
    const float* wr3   = (const float*)d_in[7];
    float* out = (float*)d_out;

    const int N = in_sizes[0] / 3;
    const int grid = (N + 127) / 128;
    nerf_fused_kernel<<<grid, 128>>>(xyz, dirp, table, w1, w2, wr1, wr2, wr3, out, N);
}